// round 15
// baseline (speedup 1.0000x reference)
#include <cuda_runtime.h>
#include <cuda_bf16.h>
#include <cuda_fp16.h>
#include <cstdint>

// ---------------- problem constants ----------------
#define N_NODES 100000
#define N_EDGES 1600000
#define IN_DIM 64
#define HID 128
#define OUT_DIM 9

// ---------------- static scratch (no allocation allowed) ----------------
__device__ int g_cnt[N_NODES];
__device__ int g_start[N_NODES + 1];
__device__ int g_cursor[N_NODES];
__device__ int g_perm[N_EDGES];
__device__ int g_bsum[512];

__device__ __nv_bfloat16 g_xhi[(size_t)N_NODES * IN_DIM];
__device__ __nv_bfloat16 g_xlo[(size_t)N_NODES * IN_DIM];
__device__ __half        g_xh[(size_t)N_NODES * IN_DIM];       // fp16 gather copy of x
__device__ __nv_bfloat16 g_mhi[(size_t)N_NODES * HID];         // mean hi
__device__ __nv_bfloat16 g_mlo[(size_t)N_NODES * HID];         // mean lo
__device__ __half        g_hh[(size_t)N_NODES * HID];          // fp16 gather copy of h1/h2
__device__ __nv_bfloat16 g_hhi[(size_t)N_NODES * HID];
__device__ __nv_bfloat16 g_hlo[(size_t)N_NODES * HID];
// static weight buffers (bf16, transposed [N,K]); order: l1l_hi,l1l_lo,l1r_hi,l1r_lo, l2..., l3...
__device__ __nv_bfloat16 g_w[12][256 * 128];

// ---------------- PTX helpers (all plain sm_80+ — no 'a' features) ----------------
__device__ __forceinline__ uint32_t smem_u32(const void* p) {
    uint32_t a;
    asm("{ .reg .u64 t; cvta.to.shared.u64 t, %1; cvt.u32.u64 %0, t; }" : "=r"(a) : "l"(p));
    return a;
}

__device__ __forceinline__ void cp_async16(uint32_t dst, const void* src, int src_bytes) {
    asm volatile("cp.async.cg.shared.global [%0], [%1], 16, %2;"
                 :: "r"(dst), "l"(src), "r"(src_bytes));
}
#define CP_COMMIT() asm volatile("cp.async.commit_group;" ::: "memory")
#define CP_WAIT_1() asm volatile("cp.async.wait_group 1;" ::: "memory")

__device__ __forceinline__ void ldm_x4(uint32_t& r0, uint32_t& r1, uint32_t& r2, uint32_t& r3,
                                       uint32_t addr) {
    asm volatile("ldmatrix.sync.aligned.m8n8.x4.shared.b16 {%0,%1,%2,%3}, [%4];"
                 : "=r"(r0), "=r"(r1), "=r"(r2), "=r"(r3) : "r"(addr));
}

__device__ __forceinline__ void mma_16816(float* c, const uint32_t* a, const uint32_t* b) {
    asm volatile(
        "mma.sync.aligned.m16n8k16.row.col.f32.bf16.bf16.f32 "
        "{%0,%1,%2,%3}, {%4,%5,%6,%7}, {%8,%9}, {%0,%1,%2,%3};"
        : "+f"(c[0]), "+f"(c[1]), "+f"(c[2]), "+f"(c[3])
        : "r"(a[0]), "r"(a[1]), "r"(a[2]), "r"(a[3]), "r"(b[0]), "r"(b[1]));
}

// ---------------- CSR build kernels ----------------
__global__ void zero_int(int* __restrict__ p, int n) {
    int i = blockIdx.x * blockDim.x + threadIdx.x;
    if (i < n) p[i] = 0;
}

// 4 edges per thread via int4 (E % 4 == 0 handled with tail guard)
__global__ void hist_kernel(const int* __restrict__ dst, int* __restrict__ cnt, int E) {
    int t = blockIdx.x * blockDim.x + threadIdx.x;
    int base = t * 4;
    if (base + 4 <= E) {
        int4 d = *reinterpret_cast<const int4*>(dst + base);
        atomicAdd(&cnt[d.x], 1);
        atomicAdd(&cnt[d.y], 1);
        atomicAdd(&cnt[d.z], 1);
        atomicAdd(&cnt[d.w], 1);
    } else {
        for (int e = base; e < E; e++) atomicAdd(&cnt[dst[e]], 1);
    }
}

#define SCAN_B 256
__global__ void block_sum(const int* __restrict__ cnt, int* __restrict__ bsum, int n) {
    __shared__ int sh[SCAN_B];
    int i = blockIdx.x * SCAN_B + threadIdx.x;
    sh[threadIdx.x] = (i < n) ? cnt[i] : 0;
    __syncthreads();
    #pragma unroll
    for (int off = SCAN_B / 2; off > 0; off >>= 1) {
        if (threadIdx.x < off) sh[threadIdx.x] += sh[threadIdx.x + off];
        __syncthreads();
    }
    if (threadIdx.x == 0) bsum[blockIdx.x] = sh[0];
}

__global__ void scan_bsums(int* __restrict__ bsum, int nb, int* __restrict__ startN) {
    __shared__ int sh[512];
    int t = threadIdx.x;
    int orig = (t < nb) ? bsum[t] : 0;
    sh[t] = orig;
    __syncthreads();
    #pragma unroll
    for (int off = 1; off < 512; off <<= 1) {
        int v = (t >= off) ? sh[t - off] : 0;
        __syncthreads();
        sh[t] += v;
        __syncthreads();
    }
    if (t < nb) bsum[t] = sh[t] - orig;   // exclusive prefix
    if (t == 0) startN[0] = sh[511];      // total = E
}

__global__ void block_scan(const int* __restrict__ cnt, const int* __restrict__ boff,
                           int* __restrict__ start, int* __restrict__ cursor, int n) {
    __shared__ int sh[SCAN_B];
    int i = blockIdx.x * SCAN_B + threadIdx.x;
    int t = threadIdx.x;
    int v = (i < n) ? cnt[i] : 0;
    sh[t] = v;
    __syncthreads();
    #pragma unroll
    for (int off = 1; off < SCAN_B; off <<= 1) {
        int u = (t >= off) ? sh[t - off] : 0;
        __syncthreads();
        sh[t] += u;
        __syncthreads();
    }
    if (i < n) {
        int ex = boff[blockIdx.x] + sh[t] - v;
        start[i] = ex;
        cursor[i] = ex;
    }
}

// 4 edges per thread via int4
__global__ void fill_perm(const int* __restrict__ src, const int* __restrict__ dst,
                          int* __restrict__ cursor, int* __restrict__ perm, int E) {
    int t = blockIdx.x * blockDim.x + threadIdx.x;
    int base = t * 4;
    if (base + 4 <= E) {
        int4 d = *reinterpret_cast<const int4*>(dst + base);
        int4 s = *reinterpret_cast<const int4*>(src + base);
        perm[atomicAdd(&cursor[d.x], 1)] = s.x;
        perm[atomicAdd(&cursor[d.y], 1)] = s.y;
        perm[atomicAdd(&cursor[d.z], 1)] = s.z;
        perm[atomicAdd(&cursor[d.w], 1)] = s.w;
    } else {
        for (int e = base; e < E; e++)
            perm[atomicAdd(&cursor[dst[e]], 1)] = src[e];
    }
}

// ---------------- CSR gather-aggregate (fp16 src) + mean + bf16 hi/lo split --------
// D = feature dim (64 or 128). Each lane handles 4 fp16 features (one uint2).
// 8-edge unrolled main loop for deeper MLP (gather is L2-latency-bound).
template <int D>
__global__ __launch_bounds__(256)
void agg_f16(const __half* __restrict__ x, const int* __restrict__ start,
             const int* __restrict__ perm,
             __nv_bfloat16* __restrict__ hi, __nv_bfloat16* __restrict__ lo, int n) {
    constexpr int DV = D / 4;                 // uint2 slots per row (16 or 32)
    int gw = (blockIdx.x * blockDim.x + threadIdx.x) >> 5;
    int lane = threadIdx.x & 31;
    int node, c;
    if (DV == 32) { node = gw; c = lane; }
    else          { node = gw * 2 + (lane >> 4); c = lane & 15; }
    if (node >= n) return;
    int s = __ldg(&start[node]);
    int e = __ldg(&start[node + 1]);
    float4 acc = make_float4(0.f, 0.f, 0.f, 0.f);

    auto accum = [&](uint2 raw) {
        __half2 h0 = *reinterpret_cast<__half2*>(&raw.x);
        __half2 h1 = *reinterpret_cast<__half2*>(&raw.y);
        float2 f0 = __half22float2(h0);
        float2 f1 = __half22float2(h1);
        acc.x += f0.x; acc.y += f0.y; acc.z += f1.x; acc.w += f1.y;
    };

    const uint2* xv = reinterpret_cast<const uint2*>(x);
    int j = s;
    for (; j + 8 <= e; j += 8) {
        int p[8];
        #pragma unroll
        for (int q = 0; q < 8; q++) p[q] = __ldg(&perm[j + q]);
        uint2 r[8];
        #pragma unroll
        for (int q = 0; q < 8; q++) r[q] = __ldg(&xv[(size_t)p[q] * DV + c]);
        #pragma unroll
        for (int q = 0; q < 8; q++) accum(r[q]);
    }
    if (j + 4 <= e) {
        int p[4];
        #pragma unroll
        for (int q = 0; q < 4; q++) p[q] = __ldg(&perm[j + q]);
        uint2 r[4];
        #pragma unroll
        for (int q = 0; q < 4; q++) r[q] = __ldg(&xv[(size_t)p[q] * DV + c]);
        #pragma unroll
        for (int q = 0; q < 4; q++) accum(r[q]);
        j += 4;
    }
    for (; j < e; j++) {
        int p = __ldg(&perm[j]);
        accum(__ldg(&xv[(size_t)p * DV + c]));
    }

    float r = 1.0f / fmaxf((float)(e - s), 1.0f);
    float m[4] = {acc.x * r, acc.y * r, acc.z * r, acc.w * r};
    __nv_bfloat16 hb[4], lb[4];
    #pragma unroll
    for (int q = 0; q < 4; q++) {
        hb[q] = __float2bfloat16(m[q]);
        lb[q] = __float2bfloat16(m[q] - __bfloat162float(hb[q]));
    }
    size_t off = (size_t)node * D + c * 4;
    *(uint2*)(hi + off) = *(uint2*)hb;
    *(uint2*)(lo + off) = *(uint2*)lb;
}

// ---------------- misc split kernels ----------------
// x fp32 -> bf16 hi/lo (GEMM operand) + fp16 (gather copy)
__global__ void split_kernel(const float* __restrict__ x,
                             __nv_bfloat16* __restrict__ hi, __nv_bfloat16* __restrict__ lo,
                             __half* __restrict__ xh, int n) {
    int i = blockIdx.x * blockDim.x + threadIdx.x;
    if (i >= n) return;
    float v = x[i];
    __nv_bfloat16 h = __float2bfloat16(v);
    hi[i] = h;
    lo[i] = __float2bfloat16(v - __bfloat162float(h));
    xh[i] = __float2half_rn(v);
}

__global__ void wsplit_kernel(const float* __restrict__ W,
                              __nv_bfloat16* __restrict__ hi, __nv_bfloat16* __restrict__ lo,
                              int K, int N) {
    int idx = blockIdx.x * blockDim.x + threadIdx.x;
    if (idx >= K * N) return;
    int k = idx / N, n = idx % N;
    float v = W[idx];
    __nv_bfloat16 h = __float2bfloat16(v);
    hi[(size_t)n * K + k] = h;
    lo[(size_t)n * K + k] = __float2bfloat16(v - __bfloat162float(h));
}

// init d_out with bfc (fc bias) so fused atomics can accumulate on top
__global__ void init_out_kernel(float* __restrict__ out, const float* __restrict__ bfc, int M) {
    int i = blockIdx.x * blockDim.x + threadIdx.x;
    if (i < M * OUT_DIM) out[i] = __ldg(&bfc[i % OUT_DIM]);
}

// ---------------- mma.sync dual-A split-bf16 GEMM (2-stage pipeline) ----------------
// v = relu( A1@B1^T + A2@B2^T + bias ), 3-term bf16 split per pair:
//   segments (A1hi,B1hi)(A1hi,B1lo)(A1lo,B1hi)(A2hi,B2hi)(A2hi,B2lo)(A2lo,B2hi)
// MODE 0: write Ch fp16 (gather copy) + Chi/Clo bf16 hi/lo (next GEMM operand)
// MODE 1: FC-fused final layer: out[row][0..8] += relu(v) @ Wfc[bn-slice]
//         (out pre-initialized with bfc; Wfc fp32 [256,9] row-major)
template <int MODE>
__global__ __launch_bounds__(256, 2)
void gemm_mma(const __nv_bfloat16* __restrict__ A1hi, const __nv_bfloat16* __restrict__ A1lo,
              const __nv_bfloat16* __restrict__ A2hi, const __nv_bfloat16* __restrict__ A2lo,
              const __nv_bfloat16* __restrict__ B1hi, const __nv_bfloat16* __restrict__ B1lo,
              const __nv_bfloat16* __restrict__ B2hi, const __nv_bfloat16* __restrict__ B2lo,
              const float* __restrict__ bias, __half* __restrict__ Ch,
              __nv_bfloat16* __restrict__ Chi, __nv_bfloat16* __restrict__ Clo,
              const float* __restrict__ Wfc, float* __restrict__ outp,
              int M, int Ntot, int Kseg) {
    extern __shared__ char smem_raw[];
    char* smem = (char*)(((uintptr_t)smem_raw + 127) & ~(uintptr_t)127);
    const uint32_t sbase = smem_u32(smem);

    const int tid = threadIdx.x;
    const int wid = tid >> 5;
    const int lane = tid & 31;
    const int warp_m = wid & 3;
    const int warp_n = wid >> 2;
    const int bm = blockIdx.x * 128;
    const int bn = blockIdx.y * 128;

    const int STG = 32768;
    const int BOFF = 16384;

    const __nv_bfloat16* As[6] = {A1hi, A1hi, A1lo, A2hi, A2hi, A2lo};
    const __nv_bfloat16* Bs[6] = {B1hi, B1lo, B1hi, B2hi, B2lo, B2hi};
    const int cps = Kseg >> 6;
    const int nch = 6 * cps;

    float acc[2][8][4];
    #pragma unroll
    for (int mi = 0; mi < 2; mi++)
        #pragma unroll
        for (int ni = 0; ni < 8; ni++)
            #pragma unroll
            for (int q = 0; q < 4; q++) acc[mi][ni][q] = 0.0f;

    auto load_stage = [&](int stage, int c) {
        const int seg = c / cps;
        const int sub = c - seg * cps;
        const __nv_bfloat16* Ab = As[seg];
        const __nv_bfloat16* Bb = Bs[seg];
        const int kofs = sub << 6;
        #pragma unroll
        for (int p = 0; p < 4; p++) {
            int ci = tid + p * 256;
            int row = ci >> 3;
            int ch = ci & 7;
            uint32_t dstp = sbase + stage * STG + row * 128 + ((ch ^ (row & 7)) << 4);
            int grow = bm + row;
            int ok = (grow < M) ? 16 : 0;
            int gr = (grow < M) ? grow : (M - 1);
            cp_async16(dstp, Ab + (size_t)gr * Kseg + kofs + ch * 8, ok);
        }
        #pragma unroll
        for (int p = 0; p < 4; p++) {
            int ci = tid + p * 256;
            int row = ci >> 3;
            int ch = ci & 7;
            uint32_t dstp = sbase + stage * STG + BOFF + row * 128 + ((ch ^ (row & 7)) << 4);
            cp_async16(dstp, Bb + (size_t)(bn + row) * Kseg + kofs + ch * 8, 16);
        }
    };

    const int arow = warp_m * 32 + (lane & 15);
    const int asel = (lane >> 4);
    const int brow = warp_n * 64 + (lane & 7) + ((lane & 16) >> 1);
    const int bsel = (lane >> 3) & 1;

    load_stage(0, 0);
    CP_COMMIT();

    for (int c = 0; c < nch; c++) {
        const int s = c & 1;
        if (c + 1 < nch) load_stage(s ^ 1, c + 1);
        CP_COMMIT();
        CP_WAIT_1();
        __syncthreads();

        const uint32_t Abase = sbase + s * STG;
        const uint32_t Bbase = sbase + s * STG + BOFF;
        #pragma unroll
        for (int kc = 0; kc < 4; kc++) {
            uint32_t a[2][4];
            #pragma unroll
            for (int mi = 0; mi < 2; mi++) {
                int r = arow + mi * 16;
                uint32_t ad = Abase + r * 128 + (((kc * 2 + asel) ^ (r & 7)) << 4);
                ldm_x4(a[mi][0], a[mi][1], a[mi][2], a[mi][3], ad);
            }
            uint32_t b[8][2];
            #pragma unroll
            for (int nj = 0; nj < 4; nj++) {
                int r = brow + nj * 16;
                uint32_t bd = Bbase + r * 128 + (((kc * 2 + bsel) ^ (r & 7)) << 4);
                uint32_t t0, t1, t2, t3;
                ldm_x4(t0, t1, t2, t3, bd);
                b[nj * 2][0] = t0; b[nj * 2][1] = t1;
                b[nj * 2 + 1][0] = t2; b[nj * 2 + 1][1] = t3;
            }
            #pragma unroll
            for (int mi = 0; mi < 2; mi++)
                #pragma unroll
                for (int ni = 0; ni < 8; ni++)
                    mma_16816(acc[mi][ni], a[mi], b[ni]);
        }
        __syncthreads();
    }

    const int col0 = bn + warp_n * 64 + (lane & 3) * 2;

    if (MODE == 0) {
        #pragma unroll
        for (int mi = 0; mi < 2; mi++) {
            int row0 = bm + warp_m * 32 + mi * 16 + (lane >> 2);
            #pragma unroll
            for (int half = 0; half < 2; half++) {
                int row = row0 + half * 8;
                if (row >= M) continue;
                #pragma unroll
                for (int ni = 0; ni < 8; ni++) {
                    int col = col0 + ni * 8;
                    float v0 = acc[mi][ni][half * 2 + 0] + __ldg(&bias[col]);
                    float v1 = acc[mi][ni][half * 2 + 1] + __ldg(&bias[col + 1]);
                    v0 = fmaxf(v0, 0.0f);
                    v1 = fmaxf(v1, 0.0f);
                    *(__half2*)(Ch + (size_t)row * Ntot + col) = __floats2half2_rn(v0, v1);
                    __nv_bfloat16 h0 = __float2bfloat16(v0);
                    __nv_bfloat16 h1 = __float2bfloat16(v1);
                    __nv_bfloat16 l0 = __float2bfloat16(v0 - __bfloat162float(h0));
                    __nv_bfloat16 l1 = __float2bfloat16(v1 - __bfloat162float(h1));
                    *(__nv_bfloat162*)(Chi + (size_t)row * Ntot + col) = __nv_bfloat162(h0, h1);
                    *(__nv_bfloat162*)(Clo + (size_t)row * Ntot + col) = __nv_bfloat162(l0, l1);
                }
            }
        }
    } else {
        // FC-fused epilogue: stage THIS CTA'S slice of Wfc (rows [bn, bn+128)) and
        // bias (cols [bn, bn+128)) into smem; compute partial fc outputs; 4-lane
        // reduce; atomicAdd into outp (pre-initialized with bfc).
        float* ws = (float*)smem;                    // 128*9 floats
        float* bs = (float*)(smem + 128 * OUT_DIM * 4);
        for (int i = tid; i < 128 * OUT_DIM; i += 256)
            ws[i] = __ldg(&Wfc[(size_t)bn * OUT_DIM + i]);
        if (tid < 128) bs[tid] = __ldg(&bias[bn + tid]);
        __syncthreads();

        #pragma unroll
        for (int mi = 0; mi < 2; mi++) {
            #pragma unroll
            for (int half = 0; half < 2; half++) {
                int row = bm + warp_m * 32 + mi * 16 + (lane >> 2) + half * 8;
                float part[OUT_DIM];
                #pragma unroll
                for (int j = 0; j < OUT_DIM; j++) part[j] = 0.0f;
                #pragma unroll
                for (int ni = 0; ni < 8; ni++) {
                    int lcol = col0 - bn + ni * 8;   // local column 0..127
                    float v0 = fmaxf(acc[mi][ni][half * 2 + 0] + bs[lcol], 0.0f);
                    float v1 = fmaxf(acc[mi][ni][half * 2 + 1] + bs[lcol + 1], 0.0f);
                    const float* w0 = ws + lcol * OUT_DIM;
                    #pragma unroll
                    for (int j = 0; j < OUT_DIM; j++)
                        part[j] += v0 * w0[j] + v1 * w0[OUT_DIM + j];
                }
                #pragma unroll
                for (int j = 0; j < OUT_DIM; j++) {
                    part[j] += __shfl_xor_sync(0xffffffffu, part[j], 1);
                    part[j] += __shfl_xor_sync(0xffffffffu, part[j], 2);
                }
                if ((lane & 3) == 0 && row < M) {
                    #pragma unroll
                    for (int j = 0; j < OUT_DIM; j++)
                        atomicAdd(&outp[(size_t)row * OUT_DIM + j], part[j]);
                }
            }
        }
    }
}

// ---------------- host launch ----------------
static inline int cdiv(int a, int b) { return (a + b - 1) / b; }

extern "C" void kernel_launch(void* const* d_in, const int* in_sizes, int n_in,
                              void* d_out, int out_size) {
    const float* x   = (const float*)d_in[0];
    const int* eidx  = (const int*)d_in[1];
    const float* Wl1 = (const float*)d_in[2];
    const float* bl1 = (const float*)d_in[3];
    const float* Wr1 = (const float*)d_in[4];
    const float* Wl2 = (const float*)d_in[5];
    const float* bl2 = (const float*)d_in[6];
    const float* Wr2 = (const float*)d_in[7];
    const float* Wl3 = (const float*)d_in[8];
    const float* bl3 = (const float*)d_in[9];
    const float* Wr3 = (const float*)d_in[10];
    const float* Wfc = (const float*)d_in[11];
    const float* bfc = (const float*)d_in[12];
    float* out = (float*)d_out;

    const int M = in_sizes[0] / IN_DIM;       // 100000
    const int E = in_sizes[1] / 2;            // 1600000
    const int* src = eidx;
    const int* dst = eidx + E;

    int *cnt, *start, *cursor, *perm, *bsum;
    __nv_bfloat16 *xhi, *xlo, *mhi, *mlo, *hhi, *hlo, *w;
    __half *xh, *hh;
    cudaGetSymbolAddress((void**)&cnt, g_cnt);
    cudaGetSymbolAddress((void**)&start, g_start);
    cudaGetSymbolAddress((void**)&cursor, g_cursor);
    cudaGetSymbolAddress((void**)&perm, g_perm);
    cudaGetSymbolAddress((void**)&bsum, g_bsum);
    cudaGetSymbolAddress((void**)&xhi, g_xhi);
    cudaGetSymbolAddress((void**)&xlo, g_xlo);
    cudaGetSymbolAddress((void**)&xh, g_xh);
    cudaGetSymbolAddress((void**)&mhi, g_mhi);
    cudaGetSymbolAddress((void**)&mlo, g_mlo);
    cudaGetSymbolAddress((void**)&hh, g_hh);
    cudaGetSymbolAddress((void**)&hhi, g_hhi);
    cudaGetSymbolAddress((void**)&hlo, g_hlo);
    cudaGetSymbolAddress((void**)&w, g_w);
    const size_t WSTRIDE = 256 * 128;
    __nv_bfloat16* wp[12];
    for (int i = 0; i < 12; i++) wp[i] = w + i * WSTRIDE;

    const int T = 256;
    const int SMEM_GEMM = 2 * 32768 + 128;

    cudaFuncSetAttribute(gemm_mma<0>, cudaFuncAttributeMaxDynamicSharedMemorySize, SMEM_GEMM);
    cudaFuncSetAttribute(gemm_mma<1>, cudaFuncAttributeMaxDynamicSharedMemorySize, SMEM_GEMM);

    // ---- CSR build (once per launch; reused by all 3 layers) ----
    const int NB = cdiv(M, SCAN_B);           // 391
    zero_int<<<cdiv(M, T), T>>>(cnt, M);
    hist_kernel<<<cdiv(cdiv(E, 4), T), T>>>(dst, cnt, E);
    block_sum<<<NB, SCAN_B>>>(cnt, bsum, M);
    scan_bsums<<<1, 512>>>(bsum, NB, start + M);
    block_scan<<<NB, SCAN_B>>>(cnt, bsum, start, cursor, M);
    fill_perm<<<cdiv(cdiv(E, 4), T), T>>>(src, dst, cursor, perm, E);

    // ---- one-time splits: x and weights; init out with bfc ----
    split_kernel<<<cdiv(M * IN_DIM, T), T>>>(x, xhi, xlo, xh, M * IN_DIM);
    wsplit_kernel<<<cdiv(IN_DIM * HID, T), T>>>(Wl1, wp[0], wp[1], IN_DIM, HID);
    wsplit_kernel<<<cdiv(IN_DIM * HID, T), T>>>(Wr1, wp[2], wp[3], IN_DIM, HID);
    wsplit_kernel<<<cdiv(HID * HID, T), T>>>(Wl2, wp[4], wp[5], HID, HID);
    wsplit_kernel<<<cdiv(HID * HID, T), T>>>(Wr2, wp[6], wp[7], HID, HID);
    wsplit_kernel<<<cdiv(HID * 2 * HID, T), T>>>(Wl3, wp[8], wp[9], HID, 2 * HID);
    wsplit_kernel<<<cdiv(HID * 2 * HID, T), T>>>(Wr3, wp[10], wp[11], HID, 2 * HID);
    init_out_kernel<<<cdiv(M * OUT_DIM, T), T>>>(out, bfc, M);

    const int MT = cdiv(M, 128);   // 782 m-tiles
    const int W128 = cdiv(M * 32, T);
    const int W64  = cdiv((M / 2 + 1) * 32, T);

    // ---- layer 1: d = 64 -> 128 (gather fp16 x) ----
    agg_f16<IN_DIM><<<W64, T>>>(xh, start, perm, mhi, mlo, M);
    gemm_mma<0><<<dim3(MT, 1), 256, SMEM_GEMM>>>(
        mhi, mlo, xhi, xlo, wp[0], wp[1], wp[2], wp[3],
        bl1, hh, hhi, hlo, nullptr, nullptr, M, HID, IN_DIM);

    // ---- layer 2: d = 128 -> 128 (gather fp16 h1) ----
    agg_f16<HID><<<W128, T>>>(hh, start, perm, mhi, mlo, M);
    gemm_mma<0><<<dim3(MT, 1), 256, SMEM_GEMM>>>(
        mhi, mlo, hhi, hlo, wp[4], wp[5], wp[6], wp[7],
        bl2, hh, hhi, hlo, nullptr, nullptr, M, HID, HID);

    // ---- layer 3: d = 128 -> 256, FC head fused into epilogue ----
    agg_f16<HID><<<W128, T>>>(hh, start, perm, mhi, mlo, M);
    gemm_mma<1><<<dim3(MT, 2), 256, SMEM_GEMM>>>(
        mhi, mlo, hhi, hlo, wp[8], wp[9], wp[10], wp[11],
        bl3, nullptr, nullptr, nullptr, Wfc, out, M, 2 * HID, HID);
}

// round 16
// speedup vs baseline: 1.2318x; 1.2318x over previous
#include <cuda_runtime.h>
#include <cuda_bf16.h>
#include <cuda_fp16.h>
#include <cstdint>

// ---------------- problem constants ----------------
#define N_NODES 100000
#define N_EDGES 1600000
#define IN_DIM 64
#define HID 128
#define OUT_DIM 9

// ---------------- static scratch (no allocation allowed) ----------------
__device__ int g_cnt[N_NODES];
__device__ int g_start[N_NODES + 1];
__device__ int g_cursor[N_NODES];
__device__ int g_perm[N_EDGES];
__device__ int g_bsum[512];

__device__ __half g_xh[(size_t)N_NODES * IN_DIM];     // fp16 x (GEMM operand + gather src)
__device__ __half g_mh[(size_t)N_NODES * HID];        // fp16 mean (GEMM operand)
__device__ __half g_hh[(size_t)N_NODES * HID];        // fp16 h1/h2 (GEMM operand + gather src)
// fp16 weights, transposed [N,K]; order per layer: Wl_hi, Wl_lo, Wr_hi, Wr_lo
__device__ __half g_w[12][256 * 128];

// ---------------- PTX helpers (all plain sm_80+ — no 'a' features) ----------------
__device__ __forceinline__ uint32_t smem_u32(const void* p) {
    uint32_t a;
    asm("{ .reg .u64 t; cvta.to.shared.u64 t, %1; cvt.u32.u64 %0, t; }" : "=r"(a) : "l"(p));
    return a;
}

__device__ __forceinline__ void cp_async16(uint32_t dst, const void* src, int src_bytes) {
    asm volatile("cp.async.cg.shared.global [%0], [%1], 16, %2;"
                 :: "r"(dst), "l"(src), "r"(src_bytes));
}
#define CP_COMMIT() asm volatile("cp.async.commit_group;" ::: "memory")
#define CP_WAIT_1() asm volatile("cp.async.wait_group 1;" ::: "memory")

__device__ __forceinline__ void ldm_x4(uint32_t& r0, uint32_t& r1, uint32_t& r2, uint32_t& r3,
                                       uint32_t addr) {
    asm volatile("ldmatrix.sync.aligned.m8n8.x4.shared.b16 {%0,%1,%2,%3}, [%4];"
                 : "=r"(r0), "=r"(r1), "=r"(r2), "=r"(r3) : "r"(addr));
}

__device__ __forceinline__ void mma_16816_f16(float* c, const uint32_t* a, const uint32_t* b) {
    asm volatile(
        "mma.sync.aligned.m16n8k16.row.col.f32.f16.f16.f32 "
        "{%0,%1,%2,%3}, {%4,%5,%6,%7}, {%8,%9}, {%0,%1,%2,%3};"
        : "+f"(c[0]), "+f"(c[1]), "+f"(c[2]), "+f"(c[3])
        : "r"(a[0]), "r"(a[1]), "r"(a[2]), "r"(a[3]), "r"(b[0]), "r"(b[1]));
}

// ---------------- CSR build kernels ----------------
__global__ void zero_int(int* __restrict__ p, int n) {
    int i = blockIdx.x * blockDim.x + threadIdx.x;
    if (i < n) p[i] = 0;
}

__global__ void hist_kernel(const int* __restrict__ dst, int* __restrict__ cnt, int E) {
    int t = blockIdx.x * blockDim.x + threadIdx.x;
    int base = t * 4;
    if (base + 4 <= E) {
        int4 d = *reinterpret_cast<const int4*>(dst + base);
        atomicAdd(&cnt[d.x], 1);
        atomicAdd(&cnt[d.y], 1);
        atomicAdd(&cnt[d.z], 1);
        atomicAdd(&cnt[d.w], 1);
    } else {
        for (int e = base; e < E; e++) atomicAdd(&cnt[dst[e]], 1);
    }
}

#define SCAN_B 256
__global__ void block_sum(const int* __restrict__ cnt, int* __restrict__ bsum, int n) {
    __shared__ int sh[SCAN_B];
    int i = blockIdx.x * SCAN_B + threadIdx.x;
    sh[threadIdx.x] = (i < n) ? cnt[i] : 0;
    __syncthreads();
    #pragma unroll
    for (int off = SCAN_B / 2; off > 0; off >>= 1) {
        if (threadIdx.x < off) sh[threadIdx.x] += sh[threadIdx.x + off];
        __syncthreads();
    }
    if (threadIdx.x == 0) bsum[blockIdx.x] = sh[0];
}

__global__ void scan_bsums(int* __restrict__ bsum, int nb, int* __restrict__ startN) {
    __shared__ int sh[512];
    int t = threadIdx.x;
    int orig = (t < nb) ? bsum[t] : 0;
    sh[t] = orig;
    __syncthreads();
    #pragma unroll
    for (int off = 1; off < 512; off <<= 1) {
        int v = (t >= off) ? sh[t - off] : 0;
        __syncthreads();
        sh[t] += v;
        __syncthreads();
    }
    if (t < nb) bsum[t] = sh[t] - orig;   // exclusive prefix
    if (t == 0) startN[0] = sh[511];      // total = E
}

__global__ void block_scan(const int* __restrict__ cnt, const int* __restrict__ boff,
                           int* __restrict__ start, int* __restrict__ cursor, int n) {
    __shared__ int sh[SCAN_B];
    int i = blockIdx.x * SCAN_B + threadIdx.x;
    int t = threadIdx.x;
    int v = (i < n) ? cnt[i] : 0;
    sh[t] = v;
    __syncthreads();
    #pragma unroll
    for (int off = 1; off < SCAN_B; off <<= 1) {
        int u = (t >= off) ? sh[t - off] : 0;
        __syncthreads();
        sh[t] += u;
        __syncthreads();
    }
    if (i < n) {
        int ex = boff[blockIdx.x] + sh[t] - v;
        start[i] = ex;
        cursor[i] = ex;
    }
}

__global__ void fill_perm(const int* __restrict__ src, const int* __restrict__ dst,
                          int* __restrict__ cursor, int* __restrict__ perm, int E) {
    int t = blockIdx.x * blockDim.x + threadIdx.x;
    int base = t * 4;
    if (base + 4 <= E) {
        int4 d = *reinterpret_cast<const int4*>(dst + base);
        int4 s = *reinterpret_cast<const int4*>(src + base);
        perm[atomicAdd(&cursor[d.x], 1)] = s.x;
        perm[atomicAdd(&cursor[d.y], 1)] = s.y;
        perm[atomicAdd(&cursor[d.z], 1)] = s.z;
        perm[atomicAdd(&cursor[d.w], 1)] = s.w;
    } else {
        for (int e = base; e < E; e++)
            perm[atomicAdd(&cursor[dst[e]], 1)] = src[e];
    }
}

// ---------------- CSR gather-aggregate (fp16 src) + mean -> fp16 --------
// D = feature dim (64 or 128). Each lane handles 4 fp16 features (one uint2).
template <int D>
__global__ __launch_bounds__(256)
void agg_f16(const __half* __restrict__ x, const int* __restrict__ start,
             const int* __restrict__ perm, __half* __restrict__ mean, int n) {
    constexpr int DV = D / 4;                 // uint2 slots per row (16 or 32)
    int gw = (blockIdx.x * blockDim.x + threadIdx.x) >> 5;
    int lane = threadIdx.x & 31;
    int node, c;
    if (DV == 32) { node = gw; c = lane; }
    else          { node = gw * 2 + (lane >> 4); c = lane & 15; }
    if (node >= n) return;
    int s = __ldg(&start[node]);
    int e = __ldg(&start[node + 1]);
    float4 acc = make_float4(0.f, 0.f, 0.f, 0.f);

    auto accum = [&](uint2 raw) {
        __half2 h0 = *reinterpret_cast<__half2*>(&raw.x);
        __half2 h1 = *reinterpret_cast<__half2*>(&raw.y);
        float2 f0 = __half22float2(h0);
        float2 f1 = __half22float2(h1);
        acc.x += f0.x; acc.y += f0.y; acc.z += f1.x; acc.w += f1.y;
    };

    const uint2* xv = reinterpret_cast<const uint2*>(x);
    int j = s;
    for (; j + 8 <= e; j += 8) {
        int p[8];
        #pragma unroll
        for (int q = 0; q < 8; q++) p[q] = __ldg(&perm[j + q]);
        uint2 r[8];
        #pragma unroll
        for (int q = 0; q < 8; q++) r[q] = __ldg(&xv[(size_t)p[q] * DV + c]);
        #pragma unroll
        for (int q = 0; q < 8; q++) accum(r[q]);
    }
    if (j + 4 <= e) {
        int p[4];
        #pragma unroll
        for (int q = 0; q < 4; q++) p[q] = __ldg(&perm[j + q]);
        uint2 r[4];
        #pragma unroll
        for (int q = 0; q < 4; q++) r[q] = __ldg(&xv[(size_t)p[q] * DV + c]);
        #pragma unroll
        for (int q = 0; q < 4; q++) accum(r[q]);
        j += 4;
    }
    for (; j < e; j++) {
        int p = __ldg(&perm[j]);
        accum(__ldg(&xv[(size_t)p * DV + c]));
    }

    float r = 1.0f / fmaxf((float)(e - s), 1.0f);
    __half2 m0 = __floats2half2_rn(acc.x * r, acc.y * r);
    __half2 m1 = __floats2half2_rn(acc.z * r, acc.w * r);
    uint2 outv;
    outv.x = *reinterpret_cast<uint32_t*>(&m0);
    outv.y = *reinterpret_cast<uint32_t*>(&m1);
    *reinterpret_cast<uint2*>(mean + (size_t)node * D + c * 4) = outv;
}

// ---------------- misc split kernels ----------------
// x fp32 -> fp16 (GEMM operand + gather copy)
__global__ void split_kernel(const float* __restrict__ x, __half* __restrict__ xh, int n) {
    int i = blockIdx.x * blockDim.x + threadIdx.x;
    if (i < n) xh[i] = __float2half_rn(x[i]);
}

// weight [K,N] fp32 -> transposed [N,K] fp16 hi/lo
__global__ void wsplit_kernel(const float* __restrict__ W,
                              __half* __restrict__ hi, __half* __restrict__ lo,
                              int K, int N) {
    int idx = blockIdx.x * blockDim.x + threadIdx.x;
    if (idx >= K * N) return;
    int k = idx / N, n = idx % N;
    float v = W[idx];
    __half h = __float2half_rn(v);
    hi[(size_t)n * K + k] = h;
    lo[(size_t)n * K + k] = __float2half_rn(v - __half2float(h));
}

// init d_out with bfc (fc bias) so fused atomics can accumulate on top
__global__ void init_out_kernel(float* __restrict__ out, const float* __restrict__ bfc, int M) {
    int i = blockIdx.x * blockDim.x + threadIdx.x;
    if (i < M * OUT_DIM) out[i] = __ldg(&bfc[i % OUT_DIM]);
}

// ---------------- mma.sync dual-A 2-term fp16 GEMM (2-stage pipeline) ----------------
// v = relu( A1@(B1hi+B1lo)^T + A2@(B2hi+B2lo)^T + bias )
//   segments (A1,B1hi)(A1,B1lo)(A2,B2hi)(A2,B2lo)  -- 4 per layer
// MODE 0: write Ch fp16 (next-layer operand + gather copy)
// MODE 1: FC-fused final layer: out[row][0..8] += relu(v) @ Wfc[bn-slice]
template <int MODE>
__global__ __launch_bounds__(256, 2)
void gemm_mma(const __half* __restrict__ A1, const __half* __restrict__ A2,
              const __half* __restrict__ B1hi, const __half* __restrict__ B1lo,
              const __half* __restrict__ B2hi, const __half* __restrict__ B2lo,
              const float* __restrict__ bias, __half* __restrict__ Ch,
              const float* __restrict__ Wfc, float* __restrict__ outp,
              int M, int Ntot, int Kseg) {
    extern __shared__ char smem_raw[];
    char* smem = (char*)(((uintptr_t)smem_raw + 127) & ~(uintptr_t)127);
    const uint32_t sbase = smem_u32(smem);

    const int tid = threadIdx.x;
    const int wid = tid >> 5;
    const int lane = tid & 31;
    const int warp_m = wid & 3;
    const int warp_n = wid >> 2;
    const int bm = blockIdx.x * 128;
    const int bn = blockIdx.y * 128;

    const int STG = 32768;
    const int BOFF = 16384;

    const __half* As[4] = {A1, A1, A2, A2};
    const __half* Bs[4] = {B1hi, B1lo, B2hi, B2lo};
    const int cps = Kseg >> 6;
    const int nch = 4 * cps;

    float acc[2][8][4];
    #pragma unroll
    for (int mi = 0; mi < 2; mi++)
        #pragma unroll
        for (int ni = 0; ni < 8; ni++)
            #pragma unroll
            for (int q = 0; q < 4; q++) acc[mi][ni][q] = 0.0f;

    auto load_stage = [&](int stage, int c) {
        const int seg = c / cps;
        const int sub = c - seg * cps;
        const __half* Ab = As[seg];
        const __half* Bb = Bs[seg];
        const int kofs = sub << 6;
        #pragma unroll
        for (int p = 0; p < 4; p++) {
            int ci = tid + p * 256;
            int row = ci >> 3;
            int ch = ci & 7;
            uint32_t dstp = sbase + stage * STG + row * 128 + ((ch ^ (row & 7)) << 4);
            int grow = bm + row;
            int ok = (grow < M) ? 16 : 0;
            int gr = (grow < M) ? grow : (M - 1);
            cp_async16(dstp, Ab + (size_t)gr * Kseg + kofs + ch * 8, ok);
        }
        #pragma unroll
        for (int p = 0; p < 4; p++) {
            int ci = tid + p * 256;
            int row = ci >> 3;
            int ch = ci & 7;
            uint32_t dstp = sbase + stage * STG + BOFF + row * 128 + ((ch ^ (row & 7)) << 4);
            cp_async16(dstp, Bb + (size_t)(bn + row) * Kseg + kofs + ch * 8, 16);
        }
    };

    const int arow = warp_m * 32 + (lane & 15);
    const int asel = (lane >> 4);
    const int brow = warp_n * 64 + (lane & 7) + ((lane & 16) >> 1);
    const int bsel = (lane >> 3) & 1;

    load_stage(0, 0);
    CP_COMMIT();

    for (int c = 0; c < nch; c++) {
        const int s = c & 1;
        if (c + 1 < nch) load_stage(s ^ 1, c + 1);
        CP_COMMIT();
        CP_WAIT_1();
        __syncthreads();

        const uint32_t Abase = sbase + s * STG;
        const uint32_t Bbase = sbase + s * STG + BOFF;
        #pragma unroll
        for (int kc = 0; kc < 4; kc++) {
            uint32_t a[2][4];
            #pragma unroll
            for (int mi = 0; mi < 2; mi++) {
                int r = arow + mi * 16;
                uint32_t ad = Abase + r * 128 + (((kc * 2 + asel) ^ (r & 7)) << 4);
                ldm_x4(a[mi][0], a[mi][1], a[mi][2], a[mi][3], ad);
            }
            uint32_t b[8][2];
            #pragma unroll
            for (int nj = 0; nj < 4; nj++) {
                int r = brow + nj * 16;
                uint32_t bd = Bbase + r * 128 + (((kc * 2 + bsel) ^ (r & 7)) << 4);
                uint32_t t0, t1, t2, t3;
                ldm_x4(t0, t1, t2, t3, bd);
                b[nj * 2][0] = t0; b[nj * 2][1] = t1;
                b[nj * 2 + 1][0] = t2; b[nj * 2 + 1][1] = t3;
            }
            #pragma unroll
            for (int mi = 0; mi < 2; mi++)
                #pragma unroll
                for (int ni = 0; ni < 8; ni++)
                    mma_16816_f16(acc[mi][ni], a[mi], b[ni]);
        }
        __syncthreads();
    }

    const int col0 = bn + warp_n * 64 + (lane & 3) * 2;

    if (MODE == 0) {
        #pragma unroll
        for (int mi = 0; mi < 2; mi++) {
            int row0 = bm + warp_m * 32 + mi * 16 + (lane >> 2);
            #pragma unroll
            for (int half = 0; half < 2; half++) {
                int row = row0 + half * 8;
                if (row >= M) continue;
                #pragma unroll
                for (int ni = 0; ni < 8; ni++) {
                    int col = col0 + ni * 8;
                    float v0 = acc[mi][ni][half * 2 + 0] + __ldg(&bias[col]);
                    float v1 = acc[mi][ni][half * 2 + 1] + __ldg(&bias[col + 1]);
                    v0 = fmaxf(v0, 0.0f);
                    v1 = fmaxf(v1, 0.0f);
                    *(__half2*)(Ch + (size_t)row * Ntot + col) = __floats2half2_rn(v0, v1);
                }
            }
        }
    } else {
        // FC-fused epilogue: stage THIS CTA'S slice of Wfc (rows [bn, bn+128)) and
        // bias (cols [bn, bn+128)) into smem; partial fc outputs; 4-lane reduce;
        // atomicAdd into outp (pre-initialized with bfc).
        float* ws = (float*)smem;                    // 128*9 floats
        float* bs = (float*)(smem + 128 * OUT_DIM * 4);
        for (int i = tid; i < 128 * OUT_DIM; i += 256)
            ws[i] = __ldg(&Wfc[(size_t)bn * OUT_DIM + i]);
        if (tid < 128) bs[tid] = __ldg(&bias[bn + tid]);
        __syncthreads();

        #pragma unroll
        for (int mi = 0; mi < 2; mi++) {
            #pragma unroll
            for (int half = 0; half < 2; half++) {
                int row = bm + warp_m * 32 + mi * 16 + (lane >> 2) + half * 8;
                float part[OUT_DIM];
                #pragma unroll
                for (int j = 0; j < OUT_DIM; j++) part[j] = 0.0f;
                #pragma unroll
                for (int ni = 0; ni < 8; ni++) {
                    int lcol = col0 - bn + ni * 8;   // local column 0..127
                    float v0 = fmaxf(acc[mi][ni][half * 2 + 0] + bs[lcol], 0.0f);
                    float v1 = fmaxf(acc[mi][ni][half * 2 + 1] + bs[lcol + 1], 0.0f);
                    const float* w0 = ws + lcol * OUT_DIM;
                    #pragma unroll
                    for (int j = 0; j < OUT_DIM; j++)
                        part[j] += v0 * w0[j] + v1 * w0[OUT_DIM + j];
                }
                #pragma unroll
                for (int j = 0; j < OUT_DIM; j++) {
                    part[j] += __shfl_xor_sync(0xffffffffu, part[j], 1);
                    part[j] += __shfl_xor_sync(0xffffffffu, part[j], 2);
                }
                if ((lane & 3) == 0 && row < M) {
                    #pragma unroll
                    for (int j = 0; j < OUT_DIM; j++)
                        atomicAdd(&outp[(size_t)row * OUT_DIM + j], part[j]);
                }
            }
        }
    }
}

// ---------------- host launch ----------------
static inline int cdiv(int a, int b) { return (a + b - 1) / b; }

extern "C" void kernel_launch(void* const* d_in, const int* in_sizes, int n_in,
                              void* d_out, int out_size) {
    const float* x   = (const float*)d_in[0];
    const int* eidx  = (const int*)d_in[1];
    const float* Wl1 = (const float*)d_in[2];
    const float* bl1 = (const float*)d_in[3];
    const float* Wr1 = (const float*)d_in[4];
    const float* Wl2 = (const float*)d_in[5];
    const float* bl2 = (const float*)d_in[6];
    const float* Wr2 = (const float*)d_in[7];
    const float* Wl3 = (const float*)d_in[8];
    const float* bl3 = (const float*)d_in[9];
    const float* Wr3 = (const float*)d_in[10];
    const float* Wfc = (const float*)d_in[11];
    const float* bfc = (const float*)d_in[12];
    float* out = (float*)d_out;

    const int M = in_sizes[0] / IN_DIM;       // 100000
    const int E = in_sizes[1] / 2;            // 1600000
    const int* src = eidx;
    const int* dst = eidx + E;

    int *cnt, *start, *cursor, *perm, *bsum;
    __half *xh, *mh, *hh, *w;
    cudaGetSymbolAddress((void**)&cnt, g_cnt);
    cudaGetSymbolAddress((void**)&start, g_start);
    cudaGetSymbolAddress((void**)&cursor, g_cursor);
    cudaGetSymbolAddress((void**)&perm, g_perm);
    cudaGetSymbolAddress((void**)&bsum, g_bsum);
    cudaGetSymbolAddress((void**)&xh, g_xh);
    cudaGetSymbolAddress((void**)&mh, g_mh);
    cudaGetSymbolAddress((void**)&hh, g_hh);
    cudaGetSymbolAddress((void**)&w, g_w);
    const size_t WSTRIDE = 256 * 128;
    __half* wp[12];
    for (int i = 0; i < 12; i++) wp[i] = w + i * WSTRIDE;

    const int T = 256;
    const int SMEM_GEMM = 2 * 32768 + 128;

    cudaFuncSetAttribute(gemm_mma<0>, cudaFuncAttributeMaxDynamicSharedMemorySize, SMEM_GEMM);
    cudaFuncSetAttribute(gemm_mma<1>, cudaFuncAttributeMaxDynamicSharedMemorySize, SMEM_GEMM);

    // ---- CSR build (once per launch; reused by all 3 layers) ----
    const int NB = cdiv(M, SCAN_B);           // 391
    zero_int<<<cdiv(M, T), T>>>(cnt, M);
    hist_kernel<<<cdiv(cdiv(E, 4), T), T>>>(dst, cnt, E);
    block_sum<<<NB, SCAN_B>>>(cnt, bsum, M);
    scan_bsums<<<1, 512>>>(bsum, NB, start + M);
    block_scan<<<NB, SCAN_B>>>(cnt, bsum, start, cursor, M);
    fill_perm<<<cdiv(cdiv(E, 4), T), T>>>(src, dst, cursor, perm, E);

    // ---- one-time conversions; init out with bfc ----
    split_kernel<<<cdiv(M * IN_DIM, T), T>>>(x, xh, M * IN_DIM);
    wsplit_kernel<<<cdiv(IN_DIM * HID, T), T>>>(Wl1, wp[0], wp[1], IN_DIM, HID);
    wsplit_kernel<<<cdiv(IN_DIM * HID, T), T>>>(Wr1, wp[2], wp[3], IN_DIM, HID);
    wsplit_kernel<<<cdiv(HID * HID, T), T>>>(Wl2, wp[4], wp[5], HID, HID);
    wsplit_kernel<<<cdiv(HID * HID, T), T>>>(Wr2, wp[6], wp[7], HID, HID);
    wsplit_kernel<<<cdiv(HID * 2 * HID, T), T>>>(Wl3, wp[8], wp[9], HID, 2 * HID);
    wsplit_kernel<<<cdiv(HID * 2 * HID, T), T>>>(Wr3, wp[10], wp[11], HID, 2 * HID);
    init_out_kernel<<<cdiv(M * OUT_DIM, T), T>>>(out, bfc, M);

    const int MT = cdiv(M, 128);   // 782 m-tiles
    const int W128 = cdiv(M * 32, T);
    const int W64  = cdiv((M / 2 + 1) * 32, T);

    // ---- layer 1: d = 64 -> 128 ----
    agg_f16<IN_DIM><<<W64, T>>>(xh, start, perm, mh, M);
    gemm_mma<0><<<dim3(MT, 1), 256, SMEM_GEMM>>>(
        mh, xh, wp[0], wp[1], wp[2], wp[3],
        bl1, hh, nullptr, nullptr, M, HID, IN_DIM);

    // ---- layer 2: d = 128 -> 128 ----
    agg_f16<HID><<<W128, T>>>(hh, start, perm, mh, M);
    gemm_mma<0><<<dim3(MT, 1), 256, SMEM_GEMM>>>(
        mh, hh, wp[4], wp[5], wp[6], wp[7],
        bl2, hh, nullptr, nullptr, M, HID, HID);

    // ---- layer 3: d = 128 -> 256, FC head fused into epilogue ----
    agg_f16<HID><<<W128, T>>>(hh, start, perm, mh, M);
    gemm_mma<1><<<dim3(MT, 2), 256, SMEM_GEMM>>>(
        mh, hh, wp[8], wp[9], wp[10], wp[11],
        bl3, nullptr, Wfc, out, M, 2 * HID, HID);
}

// round 17
// speedup vs baseline: 1.4040x; 1.1398x over previous
#include <cuda_runtime.h>
#include <cuda_bf16.h>
#include <cuda_fp16.h>
#include <cstdint>

// ---------------- problem constants ----------------
#define N_NODES 100000
#define N_EDGES 1600000
#define IN_DIM 64
#define HID 128
#define OUT_DIM 9

// ---------------- static scratch (no allocation allowed) ----------------
__device__ int g_cnt[N_NODES];
__device__ int g_start[N_NODES + 1];
__device__ int g_cursor[N_NODES];
__device__ int g_perm[N_EDGES];
__device__ int g_bsum[512];

__device__ __half g_xh[(size_t)N_NODES * IN_DIM];     // fp16 x (GEMM operand + gather src)
__device__ __half g_mh[(size_t)N_NODES * HID];        // fp16 mean (GEMM operand)
__device__ __half g_hh[(size_t)N_NODES * HID];        // fp16 h1/h2 (GEMM operand + gather src)
// fp16 weights, transposed [N,K]; order per layer: Wl, Wr
__device__ __half g_w[6][256 * 128];

// ---------------- PTX helpers (all plain sm_80+ — no 'a' features) ----------------
__device__ __forceinline__ uint32_t smem_u32(const void* p) {
    uint32_t a;
    asm("{ .reg .u64 t; cvta.to.shared.u64 t, %1; cvt.u32.u64 %0, t; }" : "=r"(a) : "l"(p));
    return a;
}

__device__ __forceinline__ void cp_async16(uint32_t dst, const void* src, int src_bytes) {
    asm volatile("cp.async.cg.shared.global [%0], [%1], 16, %2;"
                 :: "r"(dst), "l"(src), "r"(src_bytes));
}
#define CP_COMMIT() asm volatile("cp.async.commit_group;" ::: "memory")
#define CP_WAIT_1() asm volatile("cp.async.wait_group 1;" ::: "memory")

__device__ __forceinline__ void ldm_x4(uint32_t& r0, uint32_t& r1, uint32_t& r2, uint32_t& r3,
                                       uint32_t addr) {
    asm volatile("ldmatrix.sync.aligned.m8n8.x4.shared.b16 {%0,%1,%2,%3}, [%4];"
                 : "=r"(r0), "=r"(r1), "=r"(r2), "=r"(r3) : "r"(addr));
}

__device__ __forceinline__ void mma_16816_f16(float* c, const uint32_t* a, const uint32_t* b) {
    asm volatile(
        "mma.sync.aligned.m16n8k16.row.col.f32.f16.f16.f32 "
        "{%0,%1,%2,%3}, {%4,%5,%6,%7}, {%8,%9}, {%0,%1,%2,%3};"
        : "+f"(c[0]), "+f"(c[1]), "+f"(c[2]), "+f"(c[3])
        : "r"(a[0]), "r"(a[1]), "r"(a[2]), "r"(a[3]), "r"(b[0]), "r"(b[1]));
}

// ---------------- CSR build kernels ----------------
__global__ void zero_int(int* __restrict__ p, int n) {
    int i = blockIdx.x * blockDim.x + threadIdx.x;
    if (i < n) p[i] = 0;
}

__global__ void hist_kernel(const int* __restrict__ dst, int* __restrict__ cnt, int E) {
    int t = blockIdx.x * blockDim.x + threadIdx.x;
    int base = t * 4;
    if (base + 4 <= E) {
        int4 d = *reinterpret_cast<const int4*>(dst + base);
        atomicAdd(&cnt[d.x], 1);
        atomicAdd(&cnt[d.y], 1);
        atomicAdd(&cnt[d.z], 1);
        atomicAdd(&cnt[d.w], 1);
    } else {
        for (int e = base; e < E; e++) atomicAdd(&cnt[dst[e]], 1);
    }
}

#define SCAN_B 256
__global__ void block_sum(const int* __restrict__ cnt, int* __restrict__ bsum, int n) {
    __shared__ int sh[SCAN_B];
    int i = blockIdx.x * SCAN_B + threadIdx.x;
    sh[threadIdx.x] = (i < n) ? cnt[i] : 0;
    __syncthreads();
    #pragma unroll
    for (int off = SCAN_B / 2; off > 0; off >>= 1) {
        if (threadIdx.x < off) sh[threadIdx.x] += sh[threadIdx.x + off];
        __syncthreads();
    }
    if (threadIdx.x == 0) bsum[blockIdx.x] = sh[0];
}

__global__ void scan_bsums(int* __restrict__ bsum, int nb, int* __restrict__ startN) {
    __shared__ int sh[512];
    int t = threadIdx.x;
    int orig = (t < nb) ? bsum[t] : 0;
    sh[t] = orig;
    __syncthreads();
    #pragma unroll
    for (int off = 1; off < 512; off <<= 1) {
        int v = (t >= off) ? sh[t - off] : 0;
        __syncthreads();
        sh[t] += v;
        __syncthreads();
    }
    if (t < nb) bsum[t] = sh[t] - orig;   // exclusive prefix
    if (t == 0) startN[0] = sh[511];      // total = E
}

__global__ void block_scan(const int* __restrict__ cnt, const int* __restrict__ boff,
                           int* __restrict__ start, int* __restrict__ cursor, int n) {
    __shared__ int sh[SCAN_B];
    int i = blockIdx.x * SCAN_B + threadIdx.x;
    int t = threadIdx.x;
    int v = (i < n) ? cnt[i] : 0;
    sh[t] = v;
    __syncthreads();
    #pragma unroll
    for (int off = 1; off < SCAN_B; off <<= 1) {
        int u = (t >= off) ? sh[t - off] : 0;
        __syncthreads();
        sh[t] += u;
        __syncthreads();
    }
    if (i < n) {
        int ex = boff[blockIdx.x] + sh[t] - v;
        start[i] = ex;
        cursor[i] = ex;
    }
}

__global__ void fill_perm(const int* __restrict__ src, const int* __restrict__ dst,
                          int* __restrict__ cursor, int* __restrict__ perm, int E) {
    int t = blockIdx.x * blockDim.x + threadIdx.x;
    int base = t * 4;
    if (base + 4 <= E) {
        int4 d = *reinterpret_cast<const int4*>(dst + base);
        int4 s = *reinterpret_cast<const int4*>(src + base);
        perm[atomicAdd(&cursor[d.x], 1)] = s.x;
        perm[atomicAdd(&cursor[d.y], 1)] = s.y;
        perm[atomicAdd(&cursor[d.z], 1)] = s.z;
        perm[atomicAdd(&cursor[d.w], 1)] = s.w;
    } else {
        for (int e = base; e < E; e++)
            perm[atomicAdd(&cursor[dst[e]], 1)] = src[e];
    }
}

// ---------------- CSR gather-aggregate (fp16 src) + mean -> fp16 --------
template <int D>
__global__ __launch_bounds__(256)
void agg_f16(const __half* __restrict__ x, const int* __restrict__ start,
             const int* __restrict__ perm, __half* __restrict__ mean, int n) {
    constexpr int DV = D / 4;                 // uint2 slots per row (16 or 32)
    int gw = (blockIdx.x * blockDim.x + threadIdx.x) >> 5;
    int lane = threadIdx.x & 31;
    int node, c;
    if (DV == 32) { node = gw; c = lane; }
    else          { node = gw * 2 + (lane >> 4); c = lane & 15; }
    if (node >= n) return;
    int s = __ldg(&start[node]);
    int e = __ldg(&start[node + 1]);
    float4 acc = make_float4(0.f, 0.f, 0.f, 0.f);

    auto accum = [&](uint2 raw) {
        __half2 h0 = *reinterpret_cast<__half2*>(&raw.x);
        __half2 h1 = *reinterpret_cast<__half2*>(&raw.y);
        float2 f0 = __half22float2(h0);
        float2 f1 = __half22float2(h1);
        acc.x += f0.x; acc.y += f0.y; acc.z += f1.x; acc.w += f1.y;
    };

    const uint2* xv = reinterpret_cast<const uint2*>(x);
    int j = s;
    for (; j + 8 <= e; j += 8) {
        int p[8];
        #pragma unroll
        for (int q = 0; q < 8; q++) p[q] = __ldg(&perm[j + q]);
        uint2 r[8];
        #pragma unroll
        for (int q = 0; q < 8; q++) r[q] = __ldg(&xv[(size_t)p[q] * DV + c]);
        #pragma unroll
        for (int q = 0; q < 8; q++) accum(r[q]);
    }
    if (j + 4 <= e) {
        int p[4];
        #pragma unroll
        for (int q = 0; q < 4; q++) p[q] = __ldg(&perm[j + q]);
        uint2 r[4];
        #pragma unroll
        for (int q = 0; q < 4; q++) r[q] = __ldg(&xv[(size_t)p[q] * DV + c]);
        #pragma unroll
        for (int q = 0; q < 4; q++) accum(r[q]);
        j += 4;
    }
    for (; j < e; j++) {
        int p = __ldg(&perm[j]);
        accum(__ldg(&xv[(size_t)p * DV + c]));
    }

    float r = 1.0f / fmaxf((float)(e - s), 1.0f);
    __half2 m0 = __floats2half2_rn(acc.x * r, acc.y * r);
    __half2 m1 = __floats2half2_rn(acc.z * r, acc.w * r);
    uint2 outv;
    outv.x = *reinterpret_cast<uint32_t*>(&m0);
    outv.y = *reinterpret_cast<uint32_t*>(&m1);
    *reinterpret_cast<uint2*>(mean + (size_t)node * D + c * 4) = outv;
}

// ---------------- misc split kernels ----------------
__global__ void split_kernel(const float* __restrict__ x, __half* __restrict__ xh, int n) {
    int i = blockIdx.x * blockDim.x + threadIdx.x;
    if (i < n) xh[i] = __float2half_rn(x[i]);
}

// weight [K,N] fp32 -> transposed [N,K] fp16
__global__ void wconv_kernel(const float* __restrict__ W, __half* __restrict__ o, int K, int N) {
    int idx = blockIdx.x * blockDim.x + threadIdx.x;
    if (idx >= K * N) return;
    int k = idx / N, n = idx % N;
    o[(size_t)n * K + k] = __float2half_rn(W[idx]);
}

// init d_out with bfc (fc bias) so fused atomics can accumulate on top
__global__ void init_out_kernel(float* __restrict__ out, const float* __restrict__ bfc, int M) {
    int i = blockIdx.x * blockDim.x + threadIdx.x;
    if (i < M * OUT_DIM) out[i] = __ldg(&bfc[i % OUT_DIM]);
}

// ---------------- mma.sync dual-A fp16 GEMM (2-stage pipeline) ----------------
// v = relu( A1@B1^T + A2@B2^T + bias )   -- 2 segments per layer
// MODE 0: write Ch fp16 (next-layer operand + gather copy)
// MODE 1: FC-fused final layer: out[row][0..8] += relu(v) @ Wfc[bn-slice]
template <int MODE>
__global__ __launch_bounds__(256, 2)
void gemm_mma(const __half* __restrict__ A1, const __half* __restrict__ A2,
              const __half* __restrict__ B1, const __half* __restrict__ B2,
              const float* __restrict__ bias, __half* __restrict__ Ch,
              const float* __restrict__ Wfc, float* __restrict__ outp,
              int M, int Ntot, int Kseg) {
    extern __shared__ char smem_raw[];
    char* smem = (char*)(((uintptr_t)smem_raw + 127) & ~(uintptr_t)127);
    const uint32_t sbase = smem_u32(smem);

    const int tid = threadIdx.x;
    const int wid = tid >> 5;
    const int lane = tid & 31;
    const int warp_m = wid & 3;
    const int warp_n = wid >> 2;
    const int bm = blockIdx.x * 128;
    const int bn = blockIdx.y * 128;

    const int STG = 32768;
    const int BOFF = 16384;

    const __half* As[2] = {A1, A2};
    const __half* Bs[2] = {B1, B2};
    const int cps = Kseg >> 6;
    const int nch = 2 * cps;

    float acc[2][8][4];
    #pragma unroll
    for (int mi = 0; mi < 2; mi++)
        #pragma unroll
        for (int ni = 0; ni < 8; ni++)
            #pragma unroll
            for (int q = 0; q < 4; q++) acc[mi][ni][q] = 0.0f;

    auto load_stage = [&](int stage, int c) {
        const int seg = c / cps;
        const int sub = c - seg * cps;
        const __half* Ab = As[seg];
        const __half* Bb = Bs[seg];
        const int kofs = sub << 6;
        #pragma unroll
        for (int p = 0; p < 4; p++) {
            int ci = tid + p * 256;
            int row = ci >> 3;
            int ch = ci & 7;
            uint32_t dstp = sbase + stage * STG + row * 128 + ((ch ^ (row & 7)) << 4);
            int grow = bm + row;
            int ok = (grow < M) ? 16 : 0;
            int gr = (grow < M) ? grow : (M - 1);
            cp_async16(dstp, Ab + (size_t)gr * Kseg + kofs + ch * 8, ok);
        }
        #pragma unroll
        for (int p = 0; p < 4; p++) {
            int ci = tid + p * 256;
            int row = ci >> 3;
            int ch = ci & 7;
            uint32_t dstp = sbase + stage * STG + BOFF + row * 128 + ((ch ^ (row & 7)) << 4);
            cp_async16(dstp, Bb + (size_t)(bn + row) * Kseg + kofs + ch * 8, 16);
        }
    };

    const int arow = warp_m * 32 + (lane & 15);
    const int asel = (lane >> 4);
    const int brow = warp_n * 64 + (lane & 7) + ((lane & 16) >> 1);
    const int bsel = (lane >> 3) & 1;

    load_stage(0, 0);
    CP_COMMIT();

    for (int c = 0; c < nch; c++) {
        const int s = c & 1;
        if (c + 1 < nch) load_stage(s ^ 1, c + 1);
        CP_COMMIT();
        CP_WAIT_1();
        __syncthreads();

        const uint32_t Abase = sbase + s * STG;
        const uint32_t Bbase = sbase + s * STG + BOFF;
        #pragma unroll
        for (int kc = 0; kc < 4; kc++) {
            uint32_t a[2][4];
            #pragma unroll
            for (int mi = 0; mi < 2; mi++) {
                int r = arow + mi * 16;
                uint32_t ad = Abase + r * 128 + (((kc * 2 + asel) ^ (r & 7)) << 4);
                ldm_x4(a[mi][0], a[mi][1], a[mi][2], a[mi][3], ad);
            }
            uint32_t b[8][2];
            #pragma unroll
            for (int nj = 0; nj < 4; nj++) {
                int r = brow + nj * 16;
                uint32_t bd = Bbase + r * 128 + (((kc * 2 + bsel) ^ (r & 7)) << 4);
                uint32_t t0, t1, t2, t3;
                ldm_x4(t0, t1, t2, t3, bd);
                b[nj * 2][0] = t0; b[nj * 2][1] = t1;
                b[nj * 2 + 1][0] = t2; b[nj * 2 + 1][1] = t3;
            }
            #pragma unroll
            for (int mi = 0; mi < 2; mi++)
                #pragma unroll
                for (int ni = 0; ni < 8; ni++)
                    mma_16816_f16(acc[mi][ni], a[mi], b[ni]);
        }
        __syncthreads();
    }

    const int col0 = bn + warp_n * 64 + (lane & 3) * 2;

    if (MODE == 0) {
        #pragma unroll
        for (int mi = 0; mi < 2; mi++) {
            int row0 = bm + warp_m * 32 + mi * 16 + (lane >> 2);
            #pragma unroll
            for (int half = 0; half < 2; half++) {
                int row = row0 + half * 8;
                if (row >= M) continue;
                #pragma unroll
                for (int ni = 0; ni < 8; ni++) {
                    int col = col0 + ni * 8;
                    float v0 = acc[mi][ni][half * 2 + 0] + __ldg(&bias[col]);
                    float v1 = acc[mi][ni][half * 2 + 1] + __ldg(&bias[col + 1]);
                    v0 = fmaxf(v0, 0.0f);
                    v1 = fmaxf(v1, 0.0f);
                    *(__half2*)(Ch + (size_t)row * Ntot + col) = __floats2half2_rn(v0, v1);
                }
            }
        }
    } else {
        // FC-fused epilogue: stage THIS CTA'S slice of Wfc (rows [bn, bn+128)) and
        // bias (cols [bn, bn+128)) into smem; partial fc outputs; 4-lane reduce;
        // atomicAdd into outp (pre-initialized with bfc).
        float* ws = (float*)smem;                    // 128*9 floats
        float* bs = (float*)(smem + 128 * OUT_DIM * 4);
        for (int i = tid; i < 128 * OUT_DIM; i += 256)
            ws[i] = __ldg(&Wfc[(size_t)bn * OUT_DIM + i]);
        if (tid < 128) bs[tid] = __ldg(&bias[bn + tid]);
        __syncthreads();

        #pragma unroll
        for (int mi = 0; mi < 2; mi++) {
            #pragma unroll
            for (int half = 0; half < 2; half++) {
                int row = bm + warp_m * 32 + mi * 16 + (lane >> 2) + half * 8;
                float part[OUT_DIM];
                #pragma unroll
                for (int j = 0; j < OUT_DIM; j++) part[j] = 0.0f;
                #pragma unroll
                for (int ni = 0; ni < 8; ni++) {
                    int lcol = col0 - bn + ni * 8;   // local column 0..127
                    float v0 = fmaxf(acc[mi][ni][half * 2 + 0] + bs[lcol], 0.0f);
                    float v1 = fmaxf(acc[mi][ni][half * 2 + 1] + bs[lcol + 1], 0.0f);
                    const float* w0 = ws + lcol * OUT_DIM;
                    #pragma unroll
                    for (int j = 0; j < OUT_DIM; j++)
                        part[j] += v0 * w0[j] + v1 * w0[OUT_DIM + j];
                }
                #pragma unroll
                for (int j = 0; j < OUT_DIM; j++) {
                    part[j] += __shfl_xor_sync(0xffffffffu, part[j], 1);
                    part[j] += __shfl_xor_sync(0xffffffffu, part[j], 2);
                }
                if ((lane & 3) == 0 && row < M) {
                    #pragma unroll
                    for (int j = 0; j < OUT_DIM; j++)
                        atomicAdd(&outp[(size_t)row * OUT_DIM + j], part[j]);
                }
            }
        }
    }
}

// ---------------- host launch ----------------
static inline int cdiv(int a, int b) { return (a + b - 1) / b; }

extern "C" void kernel_launch(void* const* d_in, const int* in_sizes, int n_in,
                              void* d_out, int out_size) {
    const float* x   = (const float*)d_in[0];
    const int* eidx  = (const int*)d_in[1];
    const float* Wl1 = (const float*)d_in[2];
    const float* bl1 = (const float*)d_in[3];
    const float* Wr1 = (const float*)d_in[4];
    const float* Wl2 = (const float*)d_in[5];
    const float* bl2 = (const float*)d_in[6];
    const float* Wr2 = (const float*)d_in[7];
    const float* Wl3 = (const float*)d_in[8];
    const float* bl3 = (const float*)d_in[9];
    const float* Wr3 = (const float*)d_in[10];
    const float* Wfc = (const float*)d_in[11];
    const float* bfc = (const float*)d_in[12];
    float* out = (float*)d_out;

    const int M = in_sizes[0] / IN_DIM;       // 100000
    const int E = in_sizes[1] / 2;            // 1600000
    const int* src = eidx;
    const int* dst = eidx + E;

    int *cnt, *start, *cursor, *perm, *bsum;
    __half *xh, *mh, *hh, *w;
    cudaGetSymbolAddress((void**)&cnt, g_cnt);
    cudaGetSymbolAddress((void**)&start, g_start);
    cudaGetSymbolAddress((void**)&cursor, g_cursor);
    cudaGetSymbolAddress((void**)&perm, g_perm);
    cudaGetSymbolAddress((void**)&bsum, g_bsum);
    cudaGetSymbolAddress((void**)&xh, g_xh);
    cudaGetSymbolAddress((void**)&mh, g_mh);
    cudaGetSymbolAddress((void**)&hh, g_hh);
    cudaGetSymbolAddress((void**)&w, g_w);
    const size_t WSTRIDE = 256 * 128;
    __half* wp[6];
    for (int i = 0; i < 6; i++) wp[i] = w + i * WSTRIDE;

    const int T = 256;
    const int SMEM_GEMM = 2 * 32768 + 128;

    cudaFuncSetAttribute(gemm_mma<0>, cudaFuncAttributeMaxDynamicSharedMemorySize, SMEM_GEMM);
    cudaFuncSetAttribute(gemm_mma<1>, cudaFuncAttributeMaxDynamicSharedMemorySize, SMEM_GEMM);

    // ---- CSR build (once per launch; reused by all 3 layers) ----
    const int NB = cdiv(M, SCAN_B);           // 391
    zero_int<<<cdiv(M, T), T>>>(cnt, M);
    hist_kernel<<<cdiv(cdiv(E, 4), T), T>>>(dst, cnt, E);
    block_sum<<<NB, SCAN_B>>>(cnt, bsum, M);
    scan_bsums<<<1, 512>>>(bsum, NB, start + M);
    block_scan<<<NB, SCAN_B>>>(cnt, bsum, start, cursor, M);
    fill_perm<<<cdiv(cdiv(E, 4), T), T>>>(src, dst, cursor, perm, E);

    // ---- one-time conversions; init out with bfc ----
    split_kernel<<<cdiv(M * IN_DIM, T), T>>>(x, xh, M * IN_DIM);
    wconv_kernel<<<cdiv(IN_DIM * HID, T), T>>>(Wl1, wp[0], IN_DIM, HID);
    wconv_kernel<<<cdiv(IN_DIM * HID, T), T>>>(Wr1, wp[1], IN_DIM, HID);
    wconv_kernel<<<cdiv(HID * HID, T), T>>>(Wl2, wp[2], HID, HID);
    wconv_kernel<<<cdiv(HID * HID, T), T>>>(Wr2, wp[3], HID, HID);
    wconv_kernel<<<cdiv(HID * 2 * HID, T), T>>>(Wl3, wp[4], HID, 2 * HID);
    wconv_kernel<<<cdiv(HID * 2 * HID, T), T>>>(Wr3, wp[5], HID, 2 * HID);
    init_out_kernel<<<cdiv(M * OUT_DIM, T), T>>>(out, bfc, M);

    const int MT = cdiv(M, 128);   // 782 m-tiles
    const int W128 = cdiv(M * 32, T);
    const int W64  = cdiv((M / 2 + 1) * 32, T);

    // ---- layer 1: d = 64 -> 128 ----
    agg_f16<IN_DIM><<<W64, T>>>(xh, start, perm, mh, M);
    gemm_mma<0><<<dim3(MT, 1), 256, SMEM_GEMM>>>(
        mh, xh, wp[0], wp[1], bl1, hh, nullptr, nullptr, M, HID, IN_DIM);

    // ---- layer 2: d = 128 -> 128 ----
    agg_f16<HID><<<W128, T>>>(hh, start, perm, mh, M);
    gemm_mma<0><<<dim3(MT, 1), 256, SMEM_GEMM>>>(
        mh, hh, wp[2], wp[3], bl2, hh, nullptr, nullptr, M, HID, HID);

    // ---- layer 3: d = 128 -> 256, FC head fused into epilogue ----
    agg_f16<HID><<<W128, T>>>(hh, start, perm, mh, M);
    gemm_mma<1><<<dim3(MT, 2), 256, SMEM_GEMM>>>(
        mh, hh, wp[4], wp[5], bl3, nullptr, Wfc, out, M, 2 * HID, HID);
}